// round 16
// baseline (speedup 1.0000x reference)
#include <cuda_runtime.h>
#include <cuda_bf16.h>

#define NB 16
#define TT 1024
#define HH 1024
#define G3 3072
#define NPOS (NB*TT)
#define NTH_ELEMS (NB*TT*HH)
#define NCTA_W 296
#define WTHR 256

typedef unsigned long long u64;

// scratch
__device__ float          g_gx[(size_t)NPOS * G3];
__device__ float          g_rh[(size_t)NPOS * HH];     // fp32 (small tiles)
__device__ float          g_z [(size_t)NPOS * HH];
__device__ __nv_bfloat16  g_xh[(size_t)NPOS * HH];
__device__ __nv_bfloat16  g_xl[(size_t)NPOS * HH];
__device__ __nv_bfloat16  g_wth[(size_t)G3 * HH];
__device__ __nv_bfloat16  g_wtl[(size_t)G3 * HH];
__device__ __nv_bfloat16  g_whh[(size_t)G3 * HH];
__device__ __nv_bfloat16  g_whl[(size_t)G3 * HH];
__device__ __nv_bfloat16  g_hh [(size_t)NPOS * HH];    // h_out bf16 hi
__device__ __nv_bfloat16  g_hl [(size_t)NPOS * HH];    // h_out bf16 lo
__device__ __nv_bfloat16  g_rhh[(size_t)NPOS * HH];    // rh bf16 hi
__device__ __nv_bfloat16  g_rhl[(size_t)NPOS * HH];    // rh bf16 lo
__device__ __nv_bfloat16  g_ihh[HH], g_ihl[HH];        // initial_h split
__device__ __nv_bfloat16  g_ch[NB * HH], g_cl[NB * HH];// carry t=0 split
__device__ unsigned g_rbits[TT];
__device__ unsigned g_poslist[NPOS];
__device__ unsigned g_waveoff[TT + 1];
__device__ unsigned g_nwaves;
__device__ unsigned g_bar;

// ---- helpers ----
__device__ __forceinline__ void fma2(u64& d, u64 a, u64 b) {
    asm("fma.rn.f32x2 %0, %1, %2, %0;" : "+l"(d) : "l"(a), "l"(b));
}
__device__ __forceinline__ u64 dup2(float x) {
    u64 r; asm("mov.b64 %0, {%1, %1};" : "=l"(r) : "f"(x)); return r;
}
__device__ __forceinline__ float2 unpk(u64 v) {
    float2 r; asm("mov.b64 {%0, %1}, %2;" : "=f"(r.x), "=f"(r.y) : "l"(v)); return r;
}
__device__ __forceinline__ float sigm(float x) {
    return 1.f / (1.f + __expf(-x));
}
__device__ __forceinline__ unsigned su32(const void* p) {
    unsigned a;
    asm("{ .reg .u64 t; cvta.to.shared.u64 t, %1; cvt.u32.u64 %0, t; }"
        : "=r"(a) : "l"(p));
    return a;
}
__device__ __forceinline__ void cpa16(void* dst_smem, const void* src) {
    unsigned d = (unsigned)__cvta_generic_to_shared(dst_smem);
    asm volatile("cp.async.cg.shared.global [%0], [%1], 16;"
                 :: "r"(d), "l"(src) : "memory");
}
#define CPA_COMMIT() asm volatile("cp.async.commit_group;" ::: "memory")
#define CPA_WAIT0()  asm volatile("cp.async.wait_group 0;" ::: "memory")

__device__ __forceinline__ void ldm_x4(unsigned addr, unsigned r[4]) {
    asm volatile("ldmatrix.sync.aligned.m8n8.x4.shared.b16 {%0,%1,%2,%3}, [%4];"
        : "=r"(r[0]), "=r"(r[1]), "=r"(r[2]), "=r"(r[3]) : "r"(addr));
}
__device__ __forceinline__ void mma16816(float d[4], const unsigned a[4],
                                         unsigned b0, unsigned b1) {
    asm volatile(
        "mma.sync.aligned.m16n8k16.row.col.f32.bf16.bf16.f32 "
        "{%0,%1,%2,%3}, {%4,%5,%6,%7}, {%8,%9}, {%0,%1,%2,%3};"
        : "+f"(d[0]), "+f"(d[1]), "+f"(d[2]), "+f"(d[3])
        : "r"(a[0]), "r"(a[1]), "r"(a[2]), "r"(a[3]), "r"(b0), "r"(b1));
}

// ---------------------------------------------------------------------------
// prep: bf16 hi/lo splits of x, w_i^T, w_h^T, initial_h, carry(t=0)
// ---------------------------------------------------------------------------
__global__ void prep_kernel(const float* __restrict__ x,
                            const float* __restrict__ w_i,
                            const float* __restrict__ w_h,
                            const float* __restrict__ initial_h,
                            const float* __restrict__ carry) {
    const size_t stride = (size_t)gridDim.x * blockDim.x;
    size_t i0 = (size_t)blockIdx.x * blockDim.x + threadIdx.x;
    for (size_t i = i0; i < (size_t)NPOS * HH; i += stride) {
        float v = x[i];
        __nv_bfloat16 h = __float2bfloat16(v);
        g_xh[i] = h;
        g_xl[i] = __float2bfloat16(v - __bfloat162float(h));
    }
    for (size_t i = i0; i < (size_t)G3 * HH; i += stride) {
        size_t k = i / G3, n = i % G3;
        float v = w_i[i];
        __nv_bfloat16 h = __float2bfloat16(v);
        g_wth[n * HH + k] = h;
        g_wtl[n * HH + k] = __float2bfloat16(v - __bfloat162float(h));
        float vh = w_h[i];
        __nv_bfloat16 hh = __float2bfloat16(vh);
        g_whh[n * HH + k] = hh;
        g_whl[n * HH + k] = __float2bfloat16(vh - __bfloat162float(hh));
    }
    for (size_t i = i0; i < HH; i += stride) {
        float v = initial_h[i];
        __nv_bfloat16 h = __float2bfloat16(v);
        g_ihh[i] = h;
        g_ihl[i] = __float2bfloat16(v - __bfloat162float(h));
    }
    for (size_t i = i0; i < (size_t)NB * HH; i += stride) {
        size_t n = i >> 10, k = i & 1023;
        float v = carry[((size_t)n * TT) * HH + k];
        __nv_bfloat16 h = __float2bfloat16(v);
        g_ch[i] = h;
        g_cl[i] = __float2bfloat16(v - __bfloat162float(h));
    }
}

// ---------------------------------------------------------------------------
// gx via mma.sync bf16x3, cp.async staging (R15, worked in gx — stride 80B)
// ---------------------------------------------------------------------------
#define STRD 40
#define GX_SMEM 81920

__global__ void __launch_bounds__(256, 1) gx_mma_kernel() {
    extern __shared__ __nv_bfloat16 sb[];
    const int tid = threadIdx.x;
    const int lane = tid & 31;
    const int wid = tid >> 5;
    const int wm = wid >> 1;
    const int wn = wid & 1;
    const int m0 = blockIdx.y * 128;
    const int n0 = blockIdx.x * 128;

    __nv_bfloat16* Ah = sb;
    __nv_bfloat16* Al = sb + 10240;
    __nv_bfloat16* Bh = sb + 20480;
    __nv_bfloat16* Bl = sb + 30720;
    const unsigned aAh = su32(Ah);
    const unsigned aBh = su32(Bh);

    float d[2][8][4];
#pragma unroll
    for (int mt = 0; mt < 2; mt++)
#pragma unroll
        for (int nt = 0; nt < 8; nt++)
#pragma unroll
            for (int j = 0; j < 4; j++) d[mt][nt][j] = 0.f;

    const unsigned aoff = (unsigned)(((lane & 15) * STRD + (lane >> 4) * 8) * 2);
    const unsigned boff = (unsigned)(((((lane & 7) + ((lane >> 4) << 3)) * STRD) +
                                     (((lane >> 3) & 1) * 8)) * 2);

    const int r = tid >> 2, sg = tid & 3;
    auto issue = [&](int kc0, int buf) {
#pragma unroll
        for (int p = 0; p < 2; p++) {
            int rr = r + 64 * p;
            size_t offa = (size_t)(m0 + rr) * HH + kc0 + sg * 8;
            size_t offb = (size_t)(n0 + rr) * HH + kc0 + sg * 8;
            int so = buf * 5120 + rr * STRD + sg * 8;
            cpa16(Ah + so, g_xh + offa);
            cpa16(Al + so, g_xl + offa);
            cpa16(Bh + so, g_wth + offb);
            cpa16(Bl + so, g_wtl + offb);
        }
        CPA_COMMIT();
    };

    issue(0, 0);

    for (int ch = 0; ch < 32; ch++) {
        const int db = ch & 1;
        CPA_WAIT0();
        __syncthreads();
        if (ch < 31) issue((ch + 1) * 32, db ^ 1);

#pragma unroll
        for (int ks = 0; ks < 2; ks++) {
            unsigned ah[2][4], al[2][4];
#pragma unroll
            for (int mt = 0; mt < 2; mt++) {
                unsigned base = aAh + (unsigned)(db * 10240 +
                                (wm * 32 + mt * 16) * 80 + ks * 32) + aoff;
                ldm_x4(base, ah[mt]);
                ldm_x4(base + 20480u, al[mt]);
            }
#pragma unroll
            for (int bt = 0; bt < 4; bt++) {
                unsigned bh[4], bl[4];
                unsigned baseb = aBh + (unsigned)(db * 10240 +
                                 (wn * 64 + bt * 16) * 80 + ks * 32) + boff;
                ldm_x4(baseb, bh);
                ldm_x4(baseb + 20480u, bl);
#pragma unroll
                for (int mt = 0; mt < 2; mt++) {
                    mma16816(d[mt][bt * 2],     ah[mt], bh[0], bh[1]);
                    mma16816(d[mt][bt * 2],     ah[mt], bl[0], bl[1]);
                    mma16816(d[mt][bt * 2],     al[mt], bh[0], bh[1]);
                    mma16816(d[mt][bt * 2 + 1], ah[mt], bh[2], bh[3]);
                    mma16816(d[mt][bt * 2 + 1], ah[mt], bl[2], bl[3]);
                    mma16816(d[mt][bt * 2 + 1], al[mt], bh[2], bh[3]);
                }
            }
        }
        __syncthreads();
    }

#pragma unroll
    for (int mt = 0; mt < 2; mt++) {
        int row = m0 + wm * 32 + mt * 16 + (lane >> 2);
#pragma unroll
        for (int nt = 0; nt < 8; nt++) {
            int col = n0 + wn * 64 + nt * 8 + (lane & 3) * 2;
            float* p0 = g_gx + (size_t)row * G3 + col;
            *(float2*)p0            = make_float2(d[mt][nt][0], d[mt][nt][1]);
            *(float2*)(p0 + 8 * G3) = make_float2(d[mt][nt][2], d[mt][nt][3]);
        }
    }
}

// ---------------------------------------------------------------------------
// setup (unchanged)
// ---------------------------------------------------------------------------
__global__ void setup_kernel(const void* __restrict__ reset_raw,
                             const float* __restrict__ initial_h,
                             float* __restrict__ out) {
    __shared__ unsigned hist[TT];
    __shared__ unsigned curs[TT];
    __shared__ unsigned rbs[TT];
    __shared__ unsigned short depth[NB][TT];
    __shared__ int s_i32, s_f32;
    const int tid = threadIdx.x;
    if (tid == 0) { s_i32 = 1; s_f32 = 1; }
    __syncthreads();
    {
        const unsigned* rw = (const unsigned*)reset_raw;
        int bad_i = 0, bad_f = 0;
        for (int q = tid; q < 4096; q += 256) {
            unsigned v = rw[q];
            if (v > 1u) bad_i = 1;
            if (v != 0u && v != 0x3F800000u) bad_f = 1;
        }
        if (bad_i) s_i32 = 0;
        if (bad_f) s_f32 = 0;
    }
    __syncthreads();
    const int rmode = s_i32 ? 0 : (s_f32 ? 1 : 2);
    const int*           r32 = (const int*)reset_raw;
    const float*         rf  = (const float*)reset_raw;
    const unsigned char* r8  = (const unsigned char*)reset_raw;

    for (int t = tid; t < TT; t += 256) {
        unsigned m = 0;
#pragma unroll
        for (int n = 0; n < NB; n++) {
            bool rv = (rmode == 0) ? (r32[n * TT + t] != 0)
                    : (rmode == 1) ? (rf[n * TT + t] != 0.f)
                                   : (r8[n * TT + t] != 0);
            m |= (unsigned)rv << n;
        }
        rbs[t] = m;
        g_rbits[t] = m;
        hist[t] = 0;
    }
    __syncthreads();
    if (tid < NB) {
        unsigned short d = 0;
        for (int t = 0; t < TT; t++) {
            if (t == 0 || ((rbs[t] >> tid) & 1u)) d = 0; else d++;
            depth[tid][t] = d;
            atomicAdd(&hist[d], 1u);
        }
    }
    __syncthreads();
    if (tid == 0) {
        unsigned acc = 0, maxd = 0;
        for (int w0 = 0; w0 < TT; w0++) {
            unsigned c = hist[w0];
            if (c) maxd = (unsigned)w0;
            curs[w0] = acc;
            g_waveoff[w0] = acc;
            acc += c;
        }
        g_waveoff[TT] = acc;
        g_nwaves = maxd + 1;
        g_bar = 0u;
    }
    __syncthreads();
    for (int p = tid; p < NPOS; p += 256) {
        int n = p >> 10, t = p & 1023;
        unsigned d = depth[n][t];
        unsigned slot = atomicAdd(&curs[d], 1u);
        g_poslist[slot] = (unsigned)p;
    }
    for (int q = tid; q < HH; q += 256)
        out[2 * (size_t)NTH_ELEMS + q] = initial_h[q];
}

// ---------------------------------------------------------------------------
__device__ __forceinline__ void grid_barrier(unsigned target) {
    __syncthreads();
    if (threadIdx.x == 0) {
        asm volatile("red.release.gpu.global.add.u32 [%0], 1;"
                     :: "l"(&g_bar) : "memory");
        unsigned v;
        do {
            asm volatile("ld.acquire.gpu.global.u32 %0, [%1];"
                         : "=r"(v) : "l"(&g_bar) : "memory");
        } while (v < target);
    }
    __syncthreads();
}

// ---------------------------------------------------------------------------
struct WaveCtx {
    const float* carry;
    const float* initial_h;
    const float* w_h;
    const float* bias;
    float* out;
    float* AsRaw;
    float (*Bs)[32][128];
    const unsigned* rbs;
    const void** rowp;
    const void** rowpl;
    unsigned* posv;
};

__device__ __forceinline__ void set_rows_f32(const WaveCtx& C, int phase,
                                             int mtile, int POSB,
                                             unsigned base, unsigned cnt) {
    const int tid = threadIdx.x;
    __syncthreads();
    if (tid < POSB) {
        int idx = mtile * POSB + tid;
        unsigned pos = 0xFFFFFFFFu;
        const float* rp = C.initial_h;
        if ((unsigned)idx < cnt) {
            pos = g_poslist[base + idx];
            int n = pos >> 10, t = (int)(pos & 1023);
            if (phase)
                rp = g_rh + (size_t)pos * HH;
            else if ((C.rbs[t] >> n) & 1u)
                rp = C.initial_h;
            else if (t == 0)
                rp = C.carry + (size_t)n * TT * HH;
            else
                rp = C.out + (size_t)(pos - 1) * HH;
        }
        C.posv[tid] = pos;
        C.rowp[tid] = rp;
    }
    __syncthreads();
}

__device__ __forceinline__ void set_rows_bf16(const WaveCtx& C, int phase,
                                              int mtile, int POSB,
                                              unsigned base, unsigned cnt) {
    const int tid = threadIdx.x;
    __syncthreads();
    if (tid < POSB) {
        int idx = mtile * POSB + tid;
        unsigned pos = 0xFFFFFFFFu;
        const __nv_bfloat16* rh = g_ihh;
        const __nv_bfloat16* rl = g_ihl;
        if ((unsigned)idx < cnt) {
            pos = g_poslist[base + idx];
            int n = pos >> 10, t = (int)(pos & 1023);
            if (phase) {
                rh = g_rhh + (size_t)pos * HH;
                rl = g_rhl + (size_t)pos * HH;
            } else if ((C.rbs[t] >> n) & 1u) {
                rh = g_ihh; rl = g_ihl;
            } else if (t == 0) {
                rh = g_ch + (size_t)n * HH;
                rl = g_cl + (size_t)n * HH;
            } else {
                rh = g_hh + (size_t)(pos - 1) * HH;
                rl = g_hl + (size_t)(pos - 1) * HH;
            }
        }
        C.posv[tid] = pos;
        C.rowp[tid]  = rh;
        C.rowpl[tid] = rl;
    }
    __syncthreads();
}

// shared epilogue for a 2-col pair; also emits bf16 splits of rh / h_next
__device__ __forceinline__ void epi_pair(const WaveCtx& C, int phase,
                                         unsigned pos, int col0,
                                         float res0, float res1) {
    float2 gx = __ldcg((const float2*)(g_gx + (size_t)pos * G3 + col0));
    float2 bb = *(const float2*)(C.bias + col0);
    if (phase == 0 && col0 < HH) {
        float z0 = sigm(gx.x + res0 + bb.x);
        float z1 = sigm(gx.y + res1 + bb.y);
        *(float2*)(g_z + (size_t)pos * HH + col0) = make_float2(z0, z1);
    } else if (phase == 0) {
        const int j0 = col0 - HH;
        int n = pos >> 10, t = (int)(pos & 1023);
        const float* hp = ((C.rbs[t] >> n) & 1u) ? C.initial_h
                        : (t == 0 ? C.carry + (size_t)n * TT * HH
                                  : C.out + (size_t)(pos - 1) * HH);
        float2 h = __ldcg((const float2*)(hp + j0));
        float r0 = sigm(gx.x + res0 + bb.x);
        float r1 = sigm(gx.y + res1 + bb.y);
        float rh0 = r0 * h.x, rh1 = r1 * h.y;
        *(float2*)(g_rh + (size_t)pos * HH + j0) = make_float2(rh0, rh1);
        __nv_bfloat16 h0 = __float2bfloat16(rh0);
        __nv_bfloat16 h1 = __float2bfloat16(rh1);
        __nv_bfloat162 hi2; hi2.x = h0; hi2.y = h1;
        __nv_bfloat162 lo2;
        lo2.x = __float2bfloat16(rh0 - __bfloat162float(h0));
        lo2.y = __float2bfloat16(rh1 - __bfloat162float(h1));
        *(__nv_bfloat162*)(g_rhh + (size_t)pos * HH + j0) = hi2;
        *(__nv_bfloat162*)(g_rhl + (size_t)pos * HH + j0) = lo2;
    } else {
        const int j0 = col0 - 2 * HH;
        int n = pos >> 10, t = (int)(pos & 1023);
        const float* hp = ((C.rbs[t] >> n) & 1u) ? C.initial_h
                        : (t == 0 ? C.carry + (size_t)n * TT * HH
                                  : C.out + (size_t)(pos - 1) * HH);
        float2 h = __ldcg((const float2*)(hp + j0));
        float2 z = __ldcg((const float2*)(g_z + (size_t)pos * HH + j0));
        float a0 = tanhf(gx.x + res0 + bb.x);
        float a1 = tanhf(gx.y + res1 + bb.y);
        float o0 = (1.f - z.x) * h.x + z.x * a0;
        float o1 = (1.f - z.y) * h.y + z.y * a1;
        float* op = C.out + (size_t)pos * HH + j0;
        *(float2*)op               = make_float2(o0, o1);
        *(float2*)(op + NTH_ELEMS) = make_float2(o0, o1);
        __nv_bfloat16 h0 = __float2bfloat16(o0);
        __nv_bfloat16 h1 = __float2bfloat16(o1);
        __nv_bfloat162 hi2; hi2.x = h0; hi2.y = h1;
        __nv_bfloat162 lo2;
        lo2.x = __float2bfloat16(o0 - __bfloat162float(h0));
        lo2.y = __float2bfloat16(o1 - __bfloat162float(h1));
        *(__nv_bfloat162*)(g_hh + (size_t)pos * HH + j0) = hi2;
        *(__nv_bfloat162*)(g_hl + (size_t)pos * HH + j0) = lo2;
    }
}

__device__ __forceinline__ void epi_seg(const WaveCtx& C, int phase,
                                        unsigned pos, int col0,
                                        u64 q0, u64 q1) {
    float2 f0 = unpk(q0), f1 = unpk(q1);
    epi_pair(C, phase, pos, col0,     f0.x, f0.y);
    epi_pair(C, phase, pos, col0 + 2, f1.x, f1.y);
}

// ---------------------------------------------------------------------------
// MMA tile (bf16x3), all-cp.async staging. MSTRD=24 (48B stride: 16B-aligned
// cp.async dst for every row; conflict-free ldmatrix — validated in R13).
// ---------------------------------------------------------------------------
#define MSTRD 24
template<int MR>
__device__ void gemm_mma(const WaveCtx& C, int phase, int mtile, int ntile,
                         unsigned base, unsigned cnt) {
    constexpr int WN   = (MR == 128) ? 2 : 4;
    constexpr int NEXT = 128 / WN;          // 64 or 32
    constexpr int NT   = NEXT / 16;         // 4 or 2
    constexpr int AL_OFF = 2 * MR * MSTRD;           // elements
    constexpr int BH_OFF = 4 * MR * MSTRD;
    constexpr int BL_OFF = BH_OFF + 2 * 128 * MSTRD;

    const int tid = threadIdx.x;
    const int lane = tid & 31;
    const int wid = tid >> 5;
    const int wm = (MR == 128) ? (wid >> 1) : (wid >> 2);
    const int wn = wid & (WN - 1);

    set_rows_bf16(C, phase, mtile, MR, base, cnt);

    const int colbase = (phase ? 2 * HH : 0) + ntile * 128;

    __nv_bfloat16* Ah = (__nv_bfloat16*)C.AsRaw;
    const unsigned aAh = su32(Ah);

    float d[2][2 * NT][4];
#pragma unroll
    for (int mt = 0; mt < 2; mt++)
#pragma unroll
        for (int nt = 0; nt < 2 * NT; nt++)
#pragma unroll
            for (int j = 0; j < 4; j++) d[mt][nt][j] = 0.f;

    const unsigned aoff = (unsigned)((lane & 15) * (MSTRD * 2) + (lane >> 4) * 16);
    const unsigned boff = (unsigned)((((lane & 7) + ((lane >> 4) << 3)) * (MSTRD * 2)) +
                                     (((lane >> 3) & 1) * 16));

    const int r  = tid >> 1;
    const int sg = tid & 1;
    const bool doA = (MR == 128) || (tid < 128);
    const __nv_bfloat16* bsrc_h = g_whh + (size_t)(colbase + r) * HH + sg * 8;
    const __nv_bfloat16* bsrc_l = g_whl + (size_t)(colbase + r) * HH + sg * 8;
    const __nv_bfloat16* asrc_h = doA ? ((const __nv_bfloat16*)C.rowp[r]  + sg * 8) : nullptr;
    const __nv_bfloat16* asrc_l = doA ? ((const __nv_bfloat16*)C.rowpl[r] + sg * 8) : nullptr;

    auto issue = [&](int k0, int buf) {
        if (doA) {
            int so = buf * (MR * MSTRD) + r * MSTRD + sg * 8;
            cpa16(Ah + so,          asrc_h + k0);
            cpa16(Ah + AL_OFF + so, asrc_l + k0);
        }
        int sob = buf * (128 * MSTRD) + r * MSTRD + sg * 8;
        cpa16(Ah + BH_OFF + sob, bsrc_h + k0);
        cpa16(Ah + BL_OFF + sob, bsrc_l + k0);
        CPA_COMMIT();
    };

    issue(0, 0);

    for (int ch = 0; ch < 64; ch++) {
        const int db = ch & 1;
        CPA_WAIT0();
        __syncthreads();
        if (ch < 63) issue((ch + 1) * 16, db ^ 1);

        unsigned ah[2][4], al[2][4];
#pragma unroll
        for (int mt = 0; mt < 2; mt++) {
            unsigned ba = aAh + (unsigned)(db * (MR * MSTRD * 2) +
                          (wm * 32 + mt * 16) * (MSTRD * 2)) + aoff;
            ldm_x4(ba, ah[mt]);
            ldm_x4(ba + (unsigned)(AL_OFF * 2), al[mt]);
        }
#pragma unroll
        for (int bt = 0; bt < NT; bt++) {
            unsigned bh4[4], bl4[4];
            unsigned bb = aAh + (unsigned)(BH_OFF * 2) +
                          (unsigned)(db * (128 * MSTRD * 2) +
                          (wn * NEXT + bt * 16) * (MSTRD * 2)) + boff;
            ldm_x4(bb, bh4);
            ldm_x4(bb + (unsigned)((BL_OFF - BH_OFF) * 2), bl4);
#pragma unroll
            for (int mt = 0; mt < 2; mt++) {
                mma16816(d[mt][bt * 2],     ah[mt], bh4[0], bh4[1]);
                mma16816(d[mt][bt * 2],     ah[mt], bl4[0], bl4[1]);
                mma16816(d[mt][bt * 2],     al[mt], bh4[0], bh4[1]);
                mma16816(d[mt][bt * 2 + 1], ah[mt], bh4[2], bh4[3]);
                mma16816(d[mt][bt * 2 + 1], ah[mt], bl4[2], bl4[3]);
                mma16816(d[mt][bt * 2 + 1], al[mt], bh4[2], bh4[3]);
            }
        }
        __syncthreads();
    }

#pragma unroll
    for (int mt = 0; mt < 2; mt++) {
#pragma unroll
        for (int half = 0; half < 2; half++) {
            const int i = wm * 32 + mt * 16 + (lane >> 2) + half * 8;
            unsigned pos = C.posv[i];
            if (pos == 0xFFFFFFFFu) continue;
#pragma unroll
            for (int nt = 0; nt < 2 * NT; nt++) {
                int col = colbase + wn * NEXT + nt * 8 + (lane & 3) * 2;
                epi_pair(C, phase, pos, col,
                         d[mt][nt][half * 2], d[mt][nt][half * 2 + 1]);
            }
        }
    }
}

// ---------------------------------------------------------------------------
// small tile: FFMA2 16 rows
// ---------------------------------------------------------------------------
__device__ void gemm_tile1(const WaveCtx& C, int phase, int mtile, int ntile,
                           unsigned base, unsigned cnt) {
    const int tid = threadIdx.x;
    const int tx = tid & 15;
    const int ty = tid >> 4;
    float (*As)[32][64] = (float(*)[32][64])C.AsRaw;

    set_rows_f32(C, phase, mtile, 16, base, cnt);

    const int colbase = (phase ? 2 * HH : 0) + ntile * 128;
    const float* wb = C.w_h + colbase;

    u64 acc[4];
#pragma unroll
    for (int j = 0; j < 4; j++) acc[j] = 0ull;

    float4 aL, bL[4];
    auto loadA = [&](int k0) {
        if (tid < 128) {
            int i = tid & 15, kc = tid >> 4;
            aL = __ldcg((const float4*)((const float*)C.rowp[i] + k0 + kc * 4));
        }
    };
    auto storeA = [&](int buf) {
        if (tid < 128) {
            int i = tid & 15, kc = tid >> 4;
            As[buf][kc * 4 + 0][i] = aL.x;
            As[buf][kc * 4 + 1][i] = aL.y;
            As[buf][kc * 4 + 2][i] = aL.z;
            As[buf][kc * 4 + 3][i] = aL.w;
        }
    };
    auto loadB = [&](int k0) {
#pragma unroll
        for (int c = 0; c < 4; c++) {
            int q = tid + 256 * c;
            int row = q >> 5, c4 = q & 31;
            bL[c] = __ldcg((const float4*)(wb + (size_t)(k0 + row) * G3 + c4 * 4));
        }
    };
    auto storeB = [&](int buf) {
#pragma unroll
        for (int c = 0; c < 4; c++) {
            int q = tid + 256 * c;
            int row = q >> 5, c4 = q & 31;
            *(float4*)&C.Bs[buf][row][c4 * 4] = bL[c];
        }
    };

    loadA(0); loadB(0);
    storeA(0); storeB(0);
    for (int it = 0; it < 32; it++) {
        __syncthreads();
        const int db = it & 1;
        if (it < 31) { loadA((it + 1) * 32); loadB((it + 1) * 32); }
#pragma unroll
        for (int kk = 0; kk < 32; kk++) {
            float av = As[db][kk][ty];
            ulonglong2 b01 = *(const ulonglong2*)&C.Bs[db][kk][tx * 4];
            ulonglong2 b23 = *(const ulonglong2*)&C.Bs[db][kk][64 + tx * 4];
            u64 ar = dup2(av);
            fma2(acc[0], ar, b01.x);
            fma2(acc[1], ar, b01.y);
            fma2(acc[2], ar, b23.x);
            fma2(acc[3], ar, b23.y);
        }
        if (it < 31) { const int nb = db ^ 1; storeA(nb); storeB(nb); }
    }

    unsigned pos = C.posv[ty];
    if (pos != 0xFFFFFFFFu) {
        epi_seg(C, phase, pos, colbase + tx * 4,      acc[0], acc[1]);
        epi_seg(C, phase, pos, colbase + 64 + tx * 4, acc[2], acc[3]);
    }
}

// ---------------------------------------------------------------------------
__global__ void __launch_bounds__(WTHR, 2) wave_kernel(
        const float* __restrict__ carry,
        const float* __restrict__ initial_h,
        const float* __restrict__ w_h,
        const float* __restrict__ bias,
        float* __restrict__ out) {
    extern __shared__ char smw[];
    WaveCtx C;
    C.AsRaw = (float*)smw;                              // union 49664 B
    C.Bs    = (float(*)[32][128])(smw + 16896);
    unsigned* rbs = (unsigned*)(smw + 49664);           // 4096 B
    C.rowp  = (const void**)(smw + 53760);              // 1024 B
    C.rowpl = (const void**)(smw + 54784);              // 1024 B
    C.posv  = (unsigned*)(smw + 55808);                 //  512 B
    C.rbs = rbs;
    C.carry = carry; C.initial_h = initial_h;
    C.w_h = w_h; C.bias = bias; C.out = out;

    const int tid = threadIdx.x;
    for (int t = tid; t < TT; t += WTHR) rbs[t] = g_rbits[t];
    __syncthreads();

    const unsigned nw = g_nwaves;
    unsigned bar_t = 0;

    for (unsigned wv = 0; wv < nw; wv++) {
        const unsigned base = g_waveoff[wv];
        const unsigned cnt  = g_waveoff[wv + 1] - base;
        const int kind = (cnt >= 1536) ? 2 : (cnt >= 128 ? 1 : 0);
        const int mt = (kind == 2) ? (int)((cnt + 127) >> 7)
                     : (kind == 1) ? (int)((cnt + 63) >> 6)
                                   : (int)((cnt + 15) >> 4);

        for (int tile = blockIdx.x; tile < mt * 16; tile += NCTA_W) {
            if (kind == 2)      gemm_mma<128>(C, 0, tile >> 4, tile & 15, base, cnt);
            else if (kind == 1) gemm_mma<64>(C, 0, tile >> 4, tile & 15, base, cnt);
            else                gemm_tile1(C, 0, tile >> 4, tile & 15, base, cnt);
        }
        bar_t += NCTA_W;
        grid_barrier(bar_t);

        for (int tile = blockIdx.x; tile < mt * 8; tile += NCTA_W) {
            if (kind == 2)      gemm_mma<128>(C, 1, tile >> 3, tile & 7, base, cnt);
            else if (kind == 1) gemm_mma<64>(C, 1, tile >> 3, tile & 7, base, cnt);
            else                gemm_tile1(C, 1, tile >> 3, tile & 7, base, cnt);
        }
        bar_t += NCTA_W;
        grid_barrier(bar_t);
    }
}

// ---------------------------------------------------------------------------
extern "C" void kernel_launch(void* const* d_in, const int* in_sizes, int n_in,
                              void* d_out, int out_size) {
    const float* x         = (const float*)d_in[0];
    const void*  reset     = d_in[1];
    const float* carry     = (const float*)d_in[2];
    const float* initial_h = (const float*)d_in[3];
    const float* w_i       = (const float*)d_in[4];
    const float* w_h       = (const float*)d_in[5];
    const float* b         = (const float*)d_in[6];
    float*       out       = (float*)d_out;
    (void)in_sizes; (void)n_in; (void)out_size;

    prep_kernel<<<2048, 256>>>(x, w_i, w_h, initial_h, carry);

    cudaFuncSetAttribute((const void*)gx_mma_kernel,
                         cudaFuncAttributeMaxDynamicSharedMemorySize, GX_SMEM);
    dim3 tgrid(G3 / 128, NPOS / 128);
    gx_mma_kernel<<<tgrid, 256, GX_SMEM>>>();

    setup_kernel<<<1, 256>>>(reset, initial_h, out);

    size_t smem = 56320;
    cudaFuncSetAttribute((const void*)wave_kernel,
                         cudaFuncAttributeMaxDynamicSharedMemorySize, (int)smem);
    wave_kernel<<<NCTA_W, WTHR, smem>>>(carry, initial_h, w_h, b, out);
}

// round 17
// speedup vs baseline: 1.4262x; 1.4262x over previous
#include <cuda_runtime.h>
#include <cuda_bf16.h>

#define NB 16
#define TT 1024
#define HH 1024
#define G3 3072
#define NPOS (NB*TT)
#define NTH_ELEMS (NB*TT*HH)
#define NCTA_W 296
#define WTHR 256

typedef unsigned long long u64;

// scratch
__device__ float          g_gx[(size_t)NPOS * G3];
__device__ float          g_rh[(size_t)NPOS * HH];
__device__ float          g_z [(size_t)NPOS * HH];
__device__ __nv_bfloat16  g_xh[(size_t)NPOS * HH];
__device__ __nv_bfloat16  g_xl[(size_t)NPOS * HH];
__device__ __nv_bfloat16  g_wth[(size_t)G3 * HH];
__device__ __nv_bfloat16  g_wtl[(size_t)G3 * HH];
__device__ __nv_bfloat16  g_whh[(size_t)G3 * HH];
__device__ __nv_bfloat16  g_whl[(size_t)G3 * HH];
__device__ float          g_preA[17 * 2048];   // rows 0..15: carry@Wzr, 16: ih@Wzr
__device__ unsigned g_rbits[TT];
__device__ unsigned g_poslist[NPOS];
__device__ unsigned g_waveoff[TT + 1];
__device__ unsigned g_nwaves;
__device__ unsigned g_bar;

// ---- helpers ----
__device__ __forceinline__ void fma2(u64& d, u64 a, u64 b) {
    asm("fma.rn.f32x2 %0, %1, %2, %0;" : "+l"(d) : "l"(a), "l"(b));
}
__device__ __forceinline__ u64 dup2(float x) {
    u64 r; asm("mov.b64 %0, {%1, %1};" : "=l"(r) : "f"(x)); return r;
}
__device__ __forceinline__ float2 unpk(u64 v) {
    float2 r; asm("mov.b64 {%0, %1}, %2;" : "=f"(r.x), "=f"(r.y) : "l"(v)); return r;
}
__device__ __forceinline__ float sigm(float x) {
    return 1.f / (1.f + __expf(-x));
}
__device__ __forceinline__ unsigned su32(const void* p) {
    unsigned a;
    asm("{ .reg .u64 t; cvta.to.shared.u64 t, %1; cvt.u32.u64 %0, t; }"
        : "=r"(a) : "l"(p));
    return a;
}
__device__ __forceinline__ void ldm_x4(unsigned addr, unsigned r[4]) {
    asm volatile("ldmatrix.sync.aligned.m8n8.x4.shared.b16 {%0,%1,%2,%3}, [%4];"
        : "=r"(r[0]), "=r"(r[1]), "=r"(r[2]), "=r"(r[3]) : "r"(addr));
}
__device__ __forceinline__ void mma16816(float d[4], const unsigned a[4],
                                         unsigned b0, unsigned b1) {
    asm volatile(
        "mma.sync.aligned.m16n8k16.row.col.f32.bf16.bf16.f32 "
        "{%0,%1,%2,%3}, {%4,%5,%6,%7}, {%8,%9}, {%0,%1,%2,%3};"
        : "+f"(d[0]), "+f"(d[1]), "+f"(d[2]), "+f"(d[3])
        : "r"(a[0]), "r"(a[1]), "r"(a[2]), "r"(a[3]), "r"(b0), "r"(b1));
}

// ---------------------------------------------------------------------------
// prep: bf16 hi/lo splits of x, w_i^T, w_h^T
// ---------------------------------------------------------------------------
__global__ void prep_kernel(const float* __restrict__ x,
                            const float* __restrict__ w_i,
                            const float* __restrict__ w_h) {
    const size_t stride = (size_t)gridDim.x * blockDim.x;
    size_t i0 = (size_t)blockIdx.x * blockDim.x + threadIdx.x;
    for (size_t i = i0; i < (size_t)NPOS * HH; i += stride) {
        float v = x[i];
        __nv_bfloat16 h = __float2bfloat16(v);
        g_xh[i] = h;
        g_xl[i] = __float2bfloat16(v - __bfloat162float(h));
    }
    for (size_t i = i0; i < (size_t)G3 * HH; i += stride) {
        size_t k = i / G3, n = i % G3;
        float v = w_i[i];
        __nv_bfloat16 h = __float2bfloat16(v);
        g_wth[n * HH + k] = h;
        g_wtl[n * HH + k] = __float2bfloat16(v - __bfloat162float(h));
        float vh = w_h[i];
        __nv_bfloat16 hh = __float2bfloat16(vh);
        g_whh[n * HH + k] = hh;
        g_whl[n * HH + k] = __float2bfloat16(vh - __bfloat162float(hh));
    }
}

// ---------------------------------------------------------------------------
// preA: 17x2048 table = {carry rows, initial_h} @ w_h[:, :2048] (fp32 serial)
// ---------------------------------------------------------------------------
__global__ void preA_kernel(const float* __restrict__ carry,
                            const float* __restrict__ initial_h,
                            const float* __restrict__ w_h) {
    int idx = blockIdx.x * blockDim.x + threadIdx.x;   // 17*2048 outputs
    if (idx >= 17 * 2048) return;
    int row = idx >> 11, col = idx & 2047;
    const float* hrow = (row == 16) ? initial_h
                                    : carry + (size_t)row * TT * HH;
    float s = 0.f;
    for (int k = 0; k < HH; k++)
        s = fmaf(hrow[k], w_h[(size_t)k * G3 + col], s);
    g_preA[idx] = s;
}

// ---------------------------------------------------------------------------
// gx via mma.sync bf16x3 (R12/R13 validated, register staging)
// ---------------------------------------------------------------------------
#define STRD 40
#define GX_SMEM 81920

__global__ void __launch_bounds__(256, 1) gx_mma_kernel() {
    extern __shared__ __nv_bfloat16 sb[];
    const int tid = threadIdx.x;
    const int lane = tid & 31;
    const int wid = tid >> 5;
    const int wm = wid >> 1;
    const int wn = wid & 1;
    const int m0 = blockIdx.y * 128;
    const int n0 = blockIdx.x * 128;

    __nv_bfloat16* Ah = sb;
    __nv_bfloat16* Al = sb + 10240;
    __nv_bfloat16* Bh = sb + 20480;
    __nv_bfloat16* Bl = sb + 30720;
    const unsigned aAh = su32(Ah);
    const unsigned aBh = su32(Bh);

    float d[2][8][4];
#pragma unroll
    for (int mt = 0; mt < 2; mt++)
#pragma unroll
        for (int nt = 0; nt < 8; nt++)
#pragma unroll
            for (int j = 0; j < 4; j++) d[mt][nt][j] = 0.f;

    const unsigned aoff = (unsigned)(((lane & 15) * STRD + (lane >> 4) * 8) * 2);
    const unsigned boff = (unsigned)(((((lane & 7) + ((lane >> 4) << 3)) * STRD) +
                                     (((lane >> 3) & 1) * 8)) * 2);

    uint4 rah[2], ral[2], rbh[2], rbl[2];
    auto loadAB = [&](int kc0) {
#pragma unroll
        for (int p = 0; p < 2; p++) {
            int q = tid + 256 * p;
            int r = q >> 2, sg = q & 3;
            size_t offa = (size_t)(m0 + r) * HH + kc0 + sg * 8;
            size_t offb = (size_t)(n0 + r) * HH + kc0 + sg * 8;
            rah[p] = *(const uint4*)(g_xh + offa);
            ral[p] = *(const uint4*)(g_xl + offa);
            rbh[p] = *(const uint4*)(g_wth + offb);
            rbl[p] = *(const uint4*)(g_wtl + offb);
        }
    };
    auto storeAB = [&](int buf) {
#pragma unroll
        for (int p = 0; p < 2; p++) {
            int q = tid + 256 * p;
            int r = q >> 2, sg = q & 3;
            int so = buf * 5120 + r * STRD + sg * 8;
            *(uint4*)(Ah + so) = rah[p];
            *(uint4*)(Al + so) = ral[p];
            *(uint4*)(Bh + so) = rbh[p];
            *(uint4*)(Bl + so) = rbl[p];
        }
    };

    loadAB(0);
    storeAB(0);

    for (int ch = 0; ch < 32; ch++) {
        __syncthreads();
        const int db = ch & 1;
        if (ch < 31) loadAB((ch + 1) * 32);

#pragma unroll
        for (int ks = 0; ks < 2; ks++) {
            unsigned ah[2][4], al[2][4];
#pragma unroll
            for (int mt = 0; mt < 2; mt++) {
                unsigned base = aAh + (unsigned)(db * 10240 +
                                (wm * 32 + mt * 16) * 80 + ks * 32) + aoff;
                ldm_x4(base, ah[mt]);
                ldm_x4(base + 20480u, al[mt]);
            }
#pragma unroll
            for (int bt = 0; bt < 4; bt++) {
                unsigned bh[4], bl[4];
                unsigned baseb = aBh + (unsigned)(db * 10240 +
                                 (wn * 64 + bt * 16) * 80 + ks * 32) + boff;
                ldm_x4(baseb, bh);
                ldm_x4(baseb + 20480u, bl);
#pragma unroll
                for (int mt = 0; mt < 2; mt++) {
                    mma16816(d[mt][bt * 2],     ah[mt], bh[0], bh[1]);
                    mma16816(d[mt][bt * 2],     ah[mt], bl[0], bl[1]);
                    mma16816(d[mt][bt * 2],     al[mt], bh[0], bh[1]);
                    mma16816(d[mt][bt * 2 + 1], ah[mt], bh[2], bh[3]);
                    mma16816(d[mt][bt * 2 + 1], ah[mt], bl[2], bl[3]);
                    mma16816(d[mt][bt * 2 + 1], al[mt], bh[2], bh[3]);
                }
            }
        }
        if (ch < 31) storeAB(db ^ 1);
    }

#pragma unroll
    for (int mt = 0; mt < 2; mt++) {
        int row = m0 + wm * 32 + mt * 16 + (lane >> 2);
#pragma unroll
        for (int nt = 0; nt < 8; nt++) {
            int col = n0 + wn * 64 + nt * 8 + (lane & 3) * 2;
            float* p0 = g_gx + (size_t)row * G3 + col;
            *(float2*)p0            = make_float2(d[mt][nt][0], d[mt][nt][1]);
            *(float2*)(p0 + 8 * G3) = make_float2(d[mt][nt][2], d[mt][nt][3]);
        }
    }
}

// ---------------------------------------------------------------------------
// setup (unchanged)
// ---------------------------------------------------------------------------
__global__ void setup_kernel(const void* __restrict__ reset_raw,
                             const float* __restrict__ initial_h,
                             float* __restrict__ out) {
    __shared__ unsigned hist[TT];
    __shared__ unsigned curs[TT];
    __shared__ unsigned rbs[TT];
    __shared__ unsigned short depth[NB][TT];
    __shared__ int s_i32, s_f32;
    const int tid = threadIdx.x;
    if (tid == 0) { s_i32 = 1; s_f32 = 1; }
    __syncthreads();
    {
        const unsigned* rw = (const unsigned*)reset_raw;
        int bad_i = 0, bad_f = 0;
        for (int q = tid; q < 4096; q += 256) {
            unsigned v = rw[q];
            if (v > 1u) bad_i = 1;
            if (v != 0u && v != 0x3F800000u) bad_f = 1;
        }
        if (bad_i) s_i32 = 0;
        if (bad_f) s_f32 = 0;
    }
    __syncthreads();
    const int rmode = s_i32 ? 0 : (s_f32 ? 1 : 2);
    const int*           r32 = (const int*)reset_raw;
    const float*         rf  = (const float*)reset_raw;
    const unsigned char* r8  = (const unsigned char*)reset_raw;

    for (int t = tid; t < TT; t += 256) {
        unsigned m = 0;
#pragma unroll
        for (int n = 0; n < NB; n++) {
            bool rv = (rmode == 0) ? (r32[n * TT + t] != 0)
                    : (rmode == 1) ? (rf[n * TT + t] != 0.f)
                                   : (r8[n * TT + t] != 0);
            m |= (unsigned)rv << n;
        }
        rbs[t] = m;
        g_rbits[t] = m;
        hist[t] = 0;
    }
    __syncthreads();
    if (tid < NB) {
        unsigned short d = 0;
        for (int t = 0; t < TT; t++) {
            if (t == 0 || ((rbs[t] >> tid) & 1u)) d = 0; else d++;
            depth[tid][t] = d;
            atomicAdd(&hist[d], 1u);
        }
    }
    __syncthreads();
    if (tid == 0) {
        unsigned acc = 0, maxd = 0;
        for (int w0 = 0; w0 < TT; w0++) {
            unsigned c = hist[w0];
            if (c) maxd = (unsigned)w0;
            curs[w0] = acc;
            g_waveoff[w0] = acc;
            acc += c;
        }
        g_waveoff[TT] = acc;
        g_nwaves = maxd + 1;
        g_bar = 0u;
    }
    __syncthreads();
    for (int p = tid; p < NPOS; p += 256) {
        int n = p >> 10, t = p & 1023;
        unsigned d = depth[n][t];
        unsigned slot = atomicAdd(&curs[d], 1u);
        g_poslist[slot] = (unsigned)p;
    }
    for (int q = tid; q < HH; q += 256)
        out[2 * (size_t)NTH_ELEMS + q] = initial_h[q];
}

// ---------------------------------------------------------------------------
__device__ __forceinline__ void grid_barrier(unsigned target) {
    __syncthreads();
    if (threadIdx.x == 0) {
        asm volatile("red.release.gpu.global.add.u32 [%0], 1;"
                     :: "l"(&g_bar) : "memory");
        unsigned v;
        do {
            asm volatile("ld.acquire.gpu.global.u32 %0, [%1];"
                         : "=r"(v) : "l"(&g_bar) : "memory");
        } while (v < target);
    }
    __syncthreads();
}

// ---------------------------------------------------------------------------
struct WaveCtx {
    const float* carry;
    const float* initial_h;
    const float* w_h;
    const float* bias;
    float* out;
    float* AsRaw;
    float (*Bs)[32][128];
    const unsigned* rbs;
    const float** rowp;
    unsigned* posv;
};

__device__ __forceinline__ void set_rows(const WaveCtx& C, int phase,
                                         int mtile, int POSB,
                                         unsigned base, unsigned cnt) {
    const int tid = threadIdx.x;
    __syncthreads();
    if (tid < POSB) {
        int idx = mtile * POSB + tid;
        unsigned pos = 0xFFFFFFFFu;
        const float* rp = C.initial_h;
        if ((unsigned)idx < cnt) {
            pos = g_poslist[base + idx];
            int n = pos >> 10, t = (int)(pos & 1023);
            if (phase)
                rp = g_rh + (size_t)pos * HH;
            else if ((C.rbs[t] >> n) & 1u)
                rp = C.initial_h;
            else if (t == 0)
                rp = C.carry + (size_t)n * TT * HH;
            else
                rp = C.out + (size_t)(pos - 1) * HH;
        }
        C.posv[tid] = pos;
        C.rowp[tid] = rp;
    }
    __syncthreads();
}

__device__ __forceinline__ void epi_pair(const WaveCtx& C, int phase,
                                         unsigned pos, int col0,
                                         const float* rowptr,
                                         float res0, float res1) {
    float2 gx = __ldcg((const float2*)(g_gx + (size_t)pos * G3 + col0));
    float2 bb = *(const float2*)(C.bias + col0);
    if (phase == 0 && col0 < HH) {
        float z0 = sigm(gx.x + res0 + bb.x);
        float z1 = sigm(gx.y + res1 + bb.y);
        *(float2*)(g_z + (size_t)pos * HH + col0) = make_float2(z0, z1);
    } else if (phase == 0) {
        const int j0 = col0 - HH;
        float2 h = __ldcg((const float2*)(rowptr + j0));
        float r0 = sigm(gx.x + res0 + bb.x);
        float r1 = sigm(gx.y + res1 + bb.y);
        *(float2*)(g_rh + (size_t)pos * HH + j0) =
            make_float2(r0 * h.x, r1 * h.y);
    } else {
        const int j0 = col0 - 2 * HH;
        int n = pos >> 10, t = (int)(pos & 1023);
        const float* hp = ((C.rbs[t] >> n) & 1u) ? C.initial_h
                        : (t == 0 ? C.carry + (size_t)n * TT * HH
                                  : C.out + (size_t)(pos - 1) * HH);
        float2 h = __ldcg((const float2*)(hp + j0));
        float2 z = __ldcg((const float2*)(g_z + (size_t)pos * HH + j0));
        float a0 = tanhf(gx.x + res0 + bb.x);
        float a1 = tanhf(gx.y + res1 + bb.y);
        float o0 = (1.f - z.x) * h.x + z.x * a0;
        float o1 = (1.f - z.y) * h.y + z.y * a1;
        float* op = C.out + (size_t)pos * HH + j0;
        *(float2*)op               = make_float2(o0, o1);
        *(float2*)(op + NTH_ELEMS) = make_float2(o0, o1);
    }
}

__device__ __forceinline__ void epi_seg(const WaveCtx& C, int phase,
                                        unsigned pos, int col0,
                                        const float* rowptr,
                                        u64 q0, u64 q1) {
    float2 f0 = unpk(q0), f1 = unpk(q1);
    epi_pair(C, phase, pos, col0,     rowptr, f0.x, f0.y);
    epi_pair(C, phase, pos, col0 + 2, rowptr, f1.x, f1.y);
}

// ---------------------------------------------------------------------------
// MMA tile (bf16x3), register staging (R13/R14 validated). K-chunk 16, 2-buf.
// MR=128: warp 32m x 64n.  MR=64: warp 32m x 32n.
// ---------------------------------------------------------------------------
#define MSTRD 24
template<int MR>
__device__ void gemm_mma_real(const WaveCtx& C, int phase, int mtile, int ntile,
                              unsigned base, unsigned cnt) {
    constexpr int WN   = (MR == 128) ? 2 : 4;
    constexpr int NEXT = 128 / WN;
    constexpr int NT   = NEXT / 16;
    const int tid = threadIdx.x;
    const int lane = tid & 31;
    const int wid = tid >> 5;
    const int wm = (MR == 128) ? (wid >> 1) : (wid >> 2);
    const int wn = wid & (WN - 1);

    set_rows(C, phase, mtile, MR, base, cnt);

    const int colbase = (phase ? 2 * HH : 0) + ntile * 128;

    __nv_bfloat16* Ah = (__nv_bfloat16*)C.AsRaw;
    const unsigned aAh = su32(Ah);

    float d[2][2 * NT][4];
#pragma unroll
    for (int mt = 0; mt < 2; mt++)
#pragma unroll
        for (int nt = 0; nt < 2 * NT; nt++)
#pragma unroll
            for (int j = 0; j < 4; j++) d[mt][nt][j] = 0.f;

    const unsigned aoff = (unsigned)((lane & 15) * (MSTRD * 2) + (lane >> 4) * 16);
    const unsigned boff = (unsigned)((((lane & 7) + ((lane >> 4) << 3)) * (MSTRD * 2)) +
                                     (((lane >> 3) & 1) * 16));

    const int r  = tid >> 1;
    const int sg = tid & 1;
    const bool doA = (MR == 128) || (tid < 128);
    const __nv_bfloat16* bsrc_h = g_whh + (size_t)(colbase + r) * HH + sg * 8;
    const __nv_bfloat16* bsrc_l = g_whl + (size_t)(colbase + r) * HH + sg * 8;

    float4 fa0, fa1;
    uint4 rbh, rbl;
    auto loadChunk = [&](int k0) {
        if (doA) {
            fa0 = __ldcg((const float4*)(C.rowp[r] + k0 + sg * 8));
            fa1 = __ldcg((const float4*)(C.rowp[r] + k0 + sg * 8 + 4));
        }
        rbh = __ldcg((const uint4*)(bsrc_h + k0));
        rbl = __ldcg((const uint4*)(bsrc_l + k0));
    };
    auto storeChunk = [&](int buf) {
        if (doA) {
            float fa[8] = {fa0.x, fa0.y, fa0.z, fa0.w, fa1.x, fa1.y, fa1.z, fa1.w};
            __align__(16) __nv_bfloat16 hh[8], ll[8];
#pragma unroll
            for (int s = 0; s < 8; s++) {
                __nv_bfloat16 h = __float2bfloat16(fa[s]);
                hh[s] = h;
                ll[s] = __float2bfloat16(fa[s] - __bfloat162float(h));
            }
            int so = buf * (MR * MSTRD) + r * MSTRD + sg * 8;
            *(uint4*)(Ah + so)           = *(const uint4*)hh;
            *(uint4*)(Ah + MR * 48 + so) = *(const uint4*)ll;
        }
        int sob = buf * 3072 + r * MSTRD + sg * 8;
        *(uint4*)(Ah + MR * 96 + sob)        = rbh;
        *(uint4*)(Ah + MR * 96 + 6144 + sob) = rbl;
    };

    loadChunk(0);
    storeChunk(0);

    for (int ch = 0; ch < 64; ch++) {
        __syncthreads();
        const int db = ch & 1;
        if (ch < 63) loadChunk((ch + 1) * 16);

        unsigned ah[2][4], al[2][4];
#pragma unroll
        for (int mt = 0; mt < 2; mt++) {
            unsigned ba = aAh + (unsigned)(db * (MR * 48) +
                          (wm * 32 + mt * 16) * (MSTRD * 2)) + aoff;
            ldm_x4(ba, ah[mt]);
            ldm_x4(ba + (unsigned)(MR * 96), al[mt]);
        }
#pragma unroll
        for (int bt = 0; bt < NT; bt++) {
            unsigned bh4[4], bl4[4];
            unsigned bb = aAh + (unsigned)(MR * 192) + (unsigned)(db * 6144 +
                          (wn * NEXT + bt * 16) * (MSTRD * 2)) + boff;
            ldm_x4(bb, bh4);
            ldm_x4(bb + 12288u, bl4);
#pragma unroll
            for (int mt = 0; mt < 2; mt++) {
                mma16816(d[mt][bt * 2],     ah[mt], bh4[0], bh4[1]);
                mma16816(d[mt][bt * 2],     ah[mt], bl4[0], bl4[1]);
                mma16816(d[mt][bt * 2],     al[mt], bh4[0], bh4[1]);
                mma16816(d[mt][bt * 2 + 1], ah[mt], bh4[2], bh4[3]);
                mma16816(d[mt][bt * 2 + 1], ah[mt], bl4[2], bl4[3]);
                mma16816(d[mt][bt * 2 + 1], al[mt], bh4[2], bh4[3]);
            }
        }
        if (ch < 63) storeChunk(db ^ 1);
    }

#pragma unroll
    for (int mt = 0; mt < 2; mt++) {
#pragma unroll
        for (int half = 0; half < 2; half++) {
            const int i = wm * 32 + mt * 16 + (lane >> 2) + half * 8;
            unsigned pos = C.posv[i];
            if (pos == 0xFFFFFFFFu) continue;
            const float* rp = C.rowp[i];
#pragma unroll
            for (int nt = 0; nt < 2 * NT; nt++) {
                int col = colbase + wn * NEXT + nt * 8 + (lane & 3) * 2;
                epi_pair(C, phase, pos, col, rp,
                         d[mt][nt][half * 2], d[mt][nt][half * 2 + 1]);
            }
        }
    }
}

// ---------------------------------------------------------------------------
// small tile: FFMA2 16 rows
// ---------------------------------------------------------------------------
__device__ void gemm_tile1(const WaveCtx& C, int phase, int mtile, int ntile,
                           unsigned base, unsigned cnt) {
    const int tid = threadIdx.x;
    const int tx = tid & 15;
    const int ty = tid >> 4;
    float (*As)[32][64] = (float(*)[32][64])C.AsRaw;

    set_rows(C, phase, mtile, 16, base, cnt);

    const int colbase = (phase ? 2 * HH : 0) + ntile * 128;
    const float* wb = C.w_h + colbase;

    u64 acc[4];
#pragma unroll
    for (int j = 0; j < 4; j++) acc[j] = 0ull;

    float4 aL, bL[4];
    auto loadA = [&](int k0) {
        if (tid < 128) {
            int i = tid & 15, kc = tid >> 4;
            aL = __ldcg((const float4*)(C.rowp[i] + k0 + kc * 4));
        }
    };
    auto storeA = [&](int buf) {
        if (tid < 128) {
            int i = tid & 15, kc = tid >> 4;
            As[buf][kc * 4 + 0][i] = aL.x;
            As[buf][kc * 4 + 1][i] = aL.y;
            As[buf][kc * 4 + 2][i] = aL.z;
            As[buf][kc * 4 + 3][i] = aL.w;
        }
    };
    auto loadB = [&](int k0) {
#pragma unroll
        for (int c = 0; c < 4; c++) {
            int q = tid + 256 * c;
            int row = q >> 5, c4 = q & 31;
            bL[c] = __ldcg((const float4*)(wb + (size_t)(k0 + row) * G3 + c4 * 4));
        }
    };
    auto storeB = [&](int buf) {
#pragma unroll
        for (int c = 0; c < 4; c++) {
            int q = tid + 256 * c;
            int row = q >> 5, c4 = q & 31;
            *(float4*)&C.Bs[buf][row][c4 * 4] = bL[c];
        }
    };

    loadA(0); loadB(0);
    storeA(0); storeB(0);
    for (int it = 0; it < 32; it++) {
        __syncthreads();
        const int db = it & 1;
        if (it < 31) { loadA((it + 1) * 32); loadB((it + 1) * 32); }
#pragma unroll
        for (int kk = 0; kk < 32; kk++) {
            float av = As[db][kk][ty];
            ulonglong2 b01 = *(const ulonglong2*)&C.Bs[db][kk][tx * 4];
            ulonglong2 b23 = *(const ulonglong2*)&C.Bs[db][kk][64 + tx * 4];
            u64 ar = dup2(av);
            fma2(acc[0], ar, b01.x);
            fma2(acc[1], ar, b01.y);
            fma2(acc[2], ar, b23.x);
            fma2(acc[3], ar, b23.y);
        }
        if (it < 31) { const int nb = db ^ 1; storeA(nb); storeB(nb); }
    }

    unsigned pos = C.posv[ty];
    if (pos != 0xFFFFFFFFu) {
        epi_seg(C, phase, pos, colbase + tx * 4,      C.rowp[ty], acc[0], acc[1]);
        epi_seg(C, phase, pos, colbase + 64 + tx * 4, C.rowp[ty], acc[2], acc[3]);
    }
}

// ---------------------------------------------------------------------------
__global__ void __launch_bounds__(WTHR, 2) wave_kernel(
        const float* __restrict__ carry,
        const float* __restrict__ initial_h,
        const float* __restrict__ w_h,
        const float* __restrict__ bias,
        float* __restrict__ out) {
    extern __shared__ char smw[];
    WaveCtx C;
    C.AsRaw = (float*)smw;
    C.Bs    = (float(*)[32][128])(smw + 16896);
    unsigned* rbs = (unsigned*)(smw + 49664);
    C.rowp  = (const float**)(smw + 53760);
    C.posv  = (unsigned*)(smw + 54784);
    C.rbs = rbs;
    C.carry = carry; C.initial_h = initial_h;
    C.w_h = w_h; C.bias = bias; C.out = out;

    const int tid = threadIdx.x;
    for (int t = tid; t < TT; t += WTHR) rbs[t] = g_rbits[t];
    __syncthreads();

    const unsigned nw = g_nwaves;
    unsigned bar_t = 0;

    for (unsigned wv = 0; wv < nw; wv++) {
        const unsigned base = g_waveoff[wv];
        const unsigned cnt  = g_waveoff[wv + 1] - base;
        const int kind = (cnt >= 1536) ? 2 : (cnt >= 128 ? 1 : 0);
        const int mt = (kind == 2) ? (int)((cnt + 127) >> 7)
                     : (kind == 1) ? (int)((cnt + 63) >> 6)
                                   : (int)((cnt + 15) >> 4);

        // ---- phase A ----
        if (wv == 0) {
            // depth-0: zr-sums come from 17-row precomputed table; no GEMM.
            const size_t total = (size_t)cnt * 512;   // 512 float2 col-pairs/pos
            for (size_t i = (size_t)blockIdx.x * WTHR + tid; i < total;
                 i += (size_t)NCTA_W * WTHR) {
                unsigned slot = (unsigned)(i >> 9);
                int c2 = ((int)i & 511) * 2;
                unsigned pos = g_poslist[base + slot];
                int n = pos >> 10, t = (int)(pos & 1023);
                bool rst = (rbs[t] >> n) & 1u;
                const float* pre = g_preA + (rst ? 16 : n) * 2048;
                const float* hp  = rst ? initial_h
                                       : carry + (size_t)n * TT * HH;
                float2 gz = __ldcg((const float2*)(g_gx + (size_t)pos * G3 + c2));
                float2 gr = __ldcg((const float2*)(g_gx + (size_t)pos * G3 + HH + c2));
                float2 pz = *(const float2*)(pre + c2);
                float2 pr = *(const float2*)(pre + HH + c2);
                float2 bz = *(const float2*)(bias + c2);
                float2 br = *(const float2*)(bias + HH + c2);
                float2 h  = *(const float2*)(hp + c2);
                float z0 = sigm(gz.x + pz.x + bz.x);
                float z1 = sigm(gz.y + pz.y + bz.y);
                float r0 = sigm(gr.x + pr.x + br.x);
                float r1 = sigm(gr.y + pr.y + br.y);
                *(float2*)(g_z  + (size_t)pos * HH + c2) = make_float2(z0, z1);
                *(float2*)(g_rh + (size_t)pos * HH + c2) =
                    make_float2(r0 * h.x, r1 * h.y);
            }
        } else {
            for (int tile = blockIdx.x; tile < mt * 16; tile += NCTA_W) {
                if (kind == 2)      gemm_mma_real<128>(C, 0, tile >> 4, tile & 15, base, cnt);
                else if (kind == 1) gemm_mma_real<64>(C, 0, tile >> 4, tile & 15, base, cnt);
                else                gemm_tile1(C, 0, tile >> 4, tile & 15, base, cnt);
            }
        }
        bar_t += NCTA_W;
        grid_barrier(bar_t);

        // ---- phase B ----
        for (int tile = blockIdx.x; tile < mt * 8; tile += NCTA_W) {
            if (kind == 2)      gemm_mma_real<128>(C, 1, tile >> 3, tile & 7, base, cnt);
            else if (kind == 1) gemm_mma_real<64>(C, 1, tile >> 3, tile & 7, base, cnt);
            else                gemm_tile1(C, 1, tile >> 3, tile & 7, base, cnt);
        }
        bar_t += NCTA_W;
        grid_barrier(bar_t);
    }
}

// ---------------------------------------------------------------------------
extern "C" void kernel_launch(void* const* d_in, const int* in_sizes, int n_in,
                              void* d_out, int out_size) {
    const float* x         = (const float*)d_in[0];
    const void*  reset     = d_in[1];
    const float* carry     = (const float*)d_in[2];
    const float* initial_h = (const float*)d_in[3];
    const float* w_i       = (const float*)d_in[4];
    const float* w_h       = (const float*)d_in[5];
    const float* b         = (const float*)d_in[6];
    float*       out       = (float*)d_out;
    (void)in_sizes; (void)n_in; (void)out_size;

    prep_kernel<<<2048, 256>>>(x, w_i, w_h);
    preA_kernel<<<(17 * 2048 + 255) / 256, 256>>>(carry, initial_h, w_h);

    cudaFuncSetAttribute((const void*)gx_mma_kernel,
                         cudaFuncAttributeMaxDynamicSharedMemorySize, GX_SMEM);
    dim3 tgrid(G3 / 128, NPOS / 128);
    gx_mma_kernel<<<tgrid, 256, GX_SMEM>>>();

    setup_kernel<<<1, 256>>>(reset, initial_h, out);

    size_t smem = 55296;
    cudaFuncSetAttribute((const void*)wave_kernel,
                         cudaFuncAttributeMaxDynamicSharedMemorySize, (int)smem);
    wave_kernel<<<NCTA_W, WTHR, smem>>>(carry, initial_h, w_h, b, out);
}